// round 10
// baseline (speedup 1.0000x reference)
#include <cuda_runtime.h>

// QCNN closed form (see R0): layer k maps x_w <- prod_{j<=w} cos(x_j + theta_k_j),
// then out = sigmoid(x @ W + b).
//
// R10: all per-thread variants plateau at 5.4-6.1us => large fixed T_ovh plus
// a compute part stretched by CTA->SM imbalance: 256 CTAs on 148 SMs puts 16
// warps on 108 SMs and 8 on the rest (2x tail). Switch to 64-thread blocks,
// grid=1024: per-SM load becomes 7-vs-6 CTAs (14 vs 12 warps, 1.17x) instead
// of 2x. Per-thread code = R7 preload ordering + R9 E-trick (the two best).

#define NW 10
#define NLAYERS 6
#define FULLMASK 0xFFFFFFFFu

__global__ __launch_bounds__(64) void qcnn_kernel(
    const float* __restrict__ inputs,   // (B, 10)
    const float* __restrict__ thetas,   // (6, 10)
    const float* __restrict__ W,        // (10, 4)
    const float* __restrict__ bias,     // (4,)
    float* __restrict__ out,            // (B, 4)
    int B)
{
    int tid = blockIdx.x * blockDim.x + threadIdx.x;
    int e = tid >> 1;          // element index
    int l = tid & 1;           // half: wires [5l, 5l+5)
    if (e >= B) return;        // warp-uniform (B*2 divisible by 64)

    int base = l * 5;

    // Inputs first: the only unique-DRAM traffic, max early MLP.
    const float* row = inputs + (size_t)e * NW + base;
    float q0 = __ldg(row + 0);
    float q1 = __ldg(row + 1);
    float q2 = __ldg(row + 2);
    float q3 = __ldg(row + 3);
    float q4 = __ldg(row + 4);

    // Thetas (broadcast, cache-resident after first warps).
    float th[NLAYERS * 5];
    #pragma unroll
    for (int k = 0; k < NLAYERS; k++)
        #pragma unroll
        for (int w = 0; w < 5; w++)
            th[k * 5 + w] = __ldg(thetas + k * NW + base + w);

    // W rows for this lane: 5 aligned float4s; bias as float2. Preloaded
    // here (R7 showed early preload beat epilogue loads).
    const float4* wp = reinterpret_cast<const float4*>(W + base * 4);
    float4 w0 = __ldg(wp + 0), w1 = __ldg(wp + 1), w2 = __ldg(wp + 2),
           w3 = __ldg(wp + 3), w4 = __ldg(wp + 4);
    float2 bv = __ldg(reinterpret_cast<const float2*>(bias) + l);

    // E = product of the peer (lower) lane's wires; lane 0 always 1.
    float E = 1.0f;

    #pragma unroll
    for (int k = 0; k < NLAYERS; k++) {
        // arg_w = E*q_w + theta  (x_w = E*q_w is the true global prefix)
        float c0 = __cosf(fmaf(E, q0, th[k * 5 + 0]));
        float c1 = __cosf(fmaf(E, q1, th[k * 5 + 1]));
        float c2 = __cosf(fmaf(E, q2, th[k * 5 + 2]));
        float c3 = __cosf(fmaf(E, q3, th[k * 5 + 3]));
        float c4 = __cosf(fmaf(E, q4, th[k * 5 + 4]));

        // Local inclusive prefix products (stay UNscaled).
        q0 = c0;
        q1 = q0 * c1;
        q2 = q1 * c2;
        q3 = q2 * c3;
        q4 = q3 * c4;

        // Lane 0's q4 is its true total (E0==1); hand it to lane 1.
        float t = __shfl_xor_sync(FULLMASK, q4, 1, 2);
        E = l ? t : 1.0f;
    }

    // Epilogue: dot with UNscaled q, then scale the 4 partials by E
    // (keeps the final shuffle off the dot chain).
    float a0 = q0 * w0.x, a1 = q0 * w0.y, a2 = q0 * w0.z, a3 = q0 * w0.w;
    a0 = fmaf(q1, w1.x, a0); a1 = fmaf(q1, w1.y, a1);
    a2 = fmaf(q1, w1.z, a2); a3 = fmaf(q1, w1.w, a3);
    a0 = fmaf(q2, w2.x, a0); a1 = fmaf(q2, w2.y, a1);
    a2 = fmaf(q2, w2.z, a2); a3 = fmaf(q2, w2.w, a3);
    a0 = fmaf(q3, w3.x, a0); a1 = fmaf(q3, w3.y, a1);
    a2 = fmaf(q3, w3.z, a2); a3 = fmaf(q3, w3.w, a3);
    a0 = fmaf(q4, w4.x, a0); a1 = fmaf(q4, w4.y, a1);
    a2 = fmaf(q4, w4.z, a2); a3 = fmaf(q4, w4.w, a3);

    a0 *= E; a1 *= E; a2 *= E; a3 *= E;

    // Cross-lane: each lane sends exactly what its peer needs (2 shuffles).
    float send0 = l ? a0 : a2;
    float send1 = l ? a1 : a3;
    float r0 = __shfl_xor_sync(FULLMASK, send0, 1, 2);
    float r1 = __shfl_xor_sync(FULLMASK, send1, 1, 2);

    float s0 = (l ? a2 : a0) + r0 + bv.x;
    float s1 = (l ? a3 : a1) + r1 + bv.y;

    float2 r;
    r.x = __frcp_rn(1.0f + __expf(-s0));
    r.y = __frcp_rn(1.0f + __expf(-s1));
    reinterpret_cast<float2*>(out)[e * 2 + l] = r;
}

extern "C" void kernel_launch(void* const* d_in, const int* in_sizes, int n_in,
                              void* d_out, int out_size) {
    const float* inputs = (const float*)d_in[0];  // (B, 10)
    const float* thetas = (const float*)d_in[1];  // (6, 10)
    const float* W      = (const float*)d_in[2];  // (10, 4)
    const float* bias   = (const float*)d_in[3];  // (4,)
    float* out = (float*)d_out;

    int B = in_sizes[0] / NW;        // 32768
    int nThreads = B * 2;            // 65536
    int threads = 64;
    int blocks = (nThreads + threads - 1) / threads;  // 1024
    qcnn_kernel<<<blocks, threads>>>(inputs, thetas, W, bias, out, B);
}

// round 12
// speedup vs baseline: 1.1192x; 1.1192x over previous
#include <cuda_runtime.h>

// QCNN closed form (see R0): layer k maps x_w <- prod_{j<=w} cos(x_j + theta_k_j),
// then out = sigmoid(x @ W + b).
//
// R12 == R11 resubmission (previous round died to a container infra failure;
// the kernel was never run). Merge of the two best-measured variants:
//  - Shape: 2 lanes/element (wires 0-4 / 5-9), 2048 warps, 256 thr x 256 blk
//    (best wall 6.176us, R8/R9).
//  - Load order: inputs first, then theta, then W/bias, ALL preloaded before
//    the loop (best kernel 5.376us, R7).
//  - Layer body: E-fused — lanes keep UNscaled local prefixes q and a scalar
//    peer-scale E; cos argument is fmaf(E, q, theta). One shuffle per layer.
//  - Epilogue: dot with unscaled q, scale by E after, 2 shuffles, per-lane
//    float2 store (outputs {0,1} on lane 0, {2,3} on lane 1).

#define NW 10
#define NLAYERS 6
#define FULLMASK 0xFFFFFFFFu

__global__ __launch_bounds__(256, 2) void qcnn_kernel(
    const float* __restrict__ inputs,   // (B, 10)
    const float* __restrict__ thetas,   // (6, 10)
    const float* __restrict__ W,        // (10, 4)
    const float* __restrict__ bias,     // (4,)
    float* __restrict__ out,            // (B, 4)
    int B)
{
    int tid = blockIdx.x * blockDim.x + threadIdx.x;
    int e = tid >> 1;          // element index
    int l = tid & 1;           // half: wires [5l, 5l+5)
    if (e >= B) return;        // warp-uniform (B*2 divisible by 256)

    int base = l * 5;

    // ---- 1) Inputs first: the only per-element global traffic. ----
    const float* row = inputs + (size_t)e * NW + base;
    float q0 = __ldg(row + 0);
    float q1 = __ldg(row + 1);
    float q2 = __ldg(row + 2);
    float q3 = __ldg(row + 3);
    float q4 = __ldg(row + 4);

    // ---- 2) Thetas (broadcast, cache-resident). ----
    float th[NLAYERS * 5];
    #pragma unroll
    for (int k = 0; k < NLAYERS; k++)
        #pragma unroll
        for (int w = 0; w < 5; w++)
            th[k * 5 + w] = __ldg(thetas + k * NW + base + w);

    // ---- 3) W rows (5 aligned float4s) + bias (float2), preloaded. ----
    const float4* wp = reinterpret_cast<const float4*>(W + base * 4);
    float4 w0 = __ldg(wp + 0), w1 = __ldg(wp + 1), w2 = __ldg(wp + 2),
           w3 = __ldg(wp + 3), w4 = __ldg(wp + 4);
    float2 bv = __ldg(reinterpret_cast<const float2*>(bias) + l);

    // ---- 4) 6 layers, pure compute. E = peer lane's total (lane 0: 1). ----
    float E = 1.0f;

    #pragma unroll
    for (int k = 0; k < NLAYERS; k++) {
        float c0 = __cosf(fmaf(E, q0, th[k * 5 + 0]));
        float c1 = __cosf(fmaf(E, q1, th[k * 5 + 1]));
        float c2 = __cosf(fmaf(E, q2, th[k * 5 + 2]));
        float c3 = __cosf(fmaf(E, q3, th[k * 5 + 3]));
        float c4 = __cosf(fmaf(E, q4, th[k * 5 + 4]));

        // Local inclusive prefix products (stay unscaled).
        q0 = c0;
        q1 = q0 * c1;
        q2 = q1 * c2;
        q3 = q2 * c3;
        q4 = q3 * c4;

        // Lane 0's q4 is its true total (E0 == 1); hand it to lane 1.
        float t = __shfl_xor_sync(FULLMASK, q4, 1, 2);
        E = l ? t : 1.0f;
    }

    // ---- 5) Epilogue: dot with unscaled q, scale by E afterward. ----
    float a0 = q0 * w0.x, a1 = q0 * w0.y, a2 = q0 * w0.z, a3 = q0 * w0.w;
    a0 = fmaf(q1, w1.x, a0); a1 = fmaf(q1, w1.y, a1);
    a2 = fmaf(q1, w1.z, a2); a3 = fmaf(q1, w1.w, a3);
    a0 = fmaf(q2, w2.x, a0); a1 = fmaf(q2, w2.y, a1);
    a2 = fmaf(q2, w2.z, a2); a3 = fmaf(q2, w2.w, a3);
    a0 = fmaf(q3, w3.x, a0); a1 = fmaf(q3, w3.y, a1);
    a2 = fmaf(q3, w3.z, a2); a3 = fmaf(q3, w3.w, a3);
    a0 = fmaf(q4, w4.x, a0); a1 = fmaf(q4, w4.y, a1);
    a2 = fmaf(q4, w4.z, a2); a3 = fmaf(q4, w4.w, a3);

    a0 *= E; a1 *= E; a2 *= E; a3 *= E;

    // Cross-lane: each lane sends exactly what its peer needs (2 shuffles).
    float send0 = l ? a0 : a2;
    float send1 = l ? a1 : a3;
    float r0 = __shfl_xor_sync(FULLMASK, send0, 1, 2);
    float r1 = __shfl_xor_sync(FULLMASK, send1, 1, 2);

    float s0 = (l ? a2 : a0) + r0 + bv.x;
    float s1 = (l ? a3 : a1) + r1 + bv.y;

    float2 r;
    r.x = __frcp_rn(1.0f + __expf(-s0));
    r.y = __frcp_rn(1.0f + __expf(-s1));
    reinterpret_cast<float2*>(out)[e * 2 + l] = r;
}

extern "C" void kernel_launch(void* const* d_in, const int* in_sizes, int n_in,
                              void* d_out, int out_size) {
    const float* inputs = (const float*)d_in[0];  // (B, 10)
    const float* thetas = (const float*)d_in[1];  // (6, 10)
    const float* W      = (const float*)d_in[2];  // (10, 4)
    const float* bias   = (const float*)d_in[3];  // (4,)
    float* out = (float*)d_out;

    int B = in_sizes[0] / NW;        // 32768
    int nThreads = B * 2;            // 65536
    int threads = 256;
    int blocks = (nThreads + threads - 1) / threads;  // 256
    qcnn_kernel<<<blocks, threads>>>(inputs, thetas, W, bias, out, B);
}